// round 2
// baseline (speedup 1.0000x reference)
#include <cuda_runtime.h>
#include <cooperative_groups.h>
namespace cg = cooperative_groups;

#define B_    128
#define S_    1024
#define EMB_  100
#define EDIM_ 256
#define H_    1024

// Scratch (device globals: allocation-free rule)
__device__ float       g_I[S_ * B_ * H_];      // [s*128+b][h]  512 MB
__device__ signed char g_Xq[S_ * B_ * EDIM_];  // quantized layer-1 acts *16
__device__ signed char g_W2q[H_ * EDIM_];      // round(W2*16)
__device__ signed char g_Wrq[H_ * H_];         // round(Wr2*16)
__device__ float       g_sum[B_ * H_];         // spike counts

// ---------------- K0: weight quantization --------------------------------
__global__ void k_quant(const float* __restrict__ W2, const float* __restrict__ Wr2) {
    int i = blockIdx.x * blockDim.x + threadIdx.x;
    if (i < H_ * EDIM_) {
        float v = rintf(W2[i] * 16.f);
        v = fminf(fmaxf(v, -15.f), 15.f);
        g_W2q[i] = (signed char)v;
    }
    if (i < H_ * H_) {
        float v = rintf(Wr2[i] * 16.f);
        v = fminf(fmaxf(v, -15.f), 15.f);
        g_Wrq[i] = (signed char)v;
    }
}

// ---------------- K1: embedding + layer1 + quant_act ----------------------
// 64 rows per CTA. smem: W1 transposed [e][257] (conflict-free), x tile [64][104].
__global__ __launch_bounds__(256) void k_embed_l1(
    const int* __restrict__ inputs, const float* __restrict__ emb,
    const float* __restrict__ W1, const float* __restrict__ b1)
{
    extern __shared__ char sm[];
    float* w1t = (float*)sm;               // [100][257] -> 102800 B (pad to 102912)
    float* xs  = (float*)(sm + 102912);    // [64][104]  -> 26624 B
    float* b1s = (float*)(sm + 129536);    // 1024 B
    int*   tok = (int*)(sm + 130560);      // 256 B

    int t = threadIdx.x;
    for (int idx = t; idx < EDIM_ * EMB_; idx += 256) {
        int h = idx / EMB_;
        int e = idx - h * EMB_;
        w1t[e * 257 + h] = W1[idx];
    }
    b1s[t] = b1[t];
    int r0 = blockIdx.x * 64;
    if (t < 64) {
        int R = r0 + t;                     // R = s*128 + b
        tok[t] = inputs[(R & 127) * S_ + (R >> 7)];
    }
    __syncthreads();
    for (int idx = t; idx < 64 * 104; idx += 256) {
        int r = idx / 104;
        int e = idx - r * 104;
        xs[idx] = (e < EMB_) ? emb[tok[r] * EMB_ + e] : 0.f;
    }
    __syncthreads();

    int h = t;  // one output channel per thread
    for (int rb = 0; rb < 8; rb++) {
        float acc[8];
#pragma unroll
        for (int i = 0; i < 8; i++) acc[i] = 0.f;
        for (int ec = 0; ec < 25; ec++) {
            float w0 = w1t[(4 * ec + 0) * 257 + h];
            float w1v = w1t[(4 * ec + 1) * 257 + h];
            float w2v = w1t[(4 * ec + 2) * 257 + h];
            float w3v = w1t[(4 * ec + 3) * 257 + h];
#pragma unroll
            for (int r8 = 0; r8 < 8; r8++) {
                const float4 x4 = *(const float4*)(xs + (rb * 8 + r8) * 104 + 4 * ec);
                acc[r8] += x4.x * w0 + x4.y * w1v + x4.z * w2v + x4.w * w3v;
            }
        }
#pragma unroll
        for (int r8 = 0; r8 < 8; r8++) {
            int R = r0 + rb * 8 + r8;
            float v = acc[r8] + b1s[h];
            v = fmaxf(v, 0.f);
            float q = fminf(rintf(v * 16.f), 15.f);
            g_Xq[R * EDIM_ + h] = (signed char)q;
        }
    }
}

// ---------------- K2: I = Xq @ W2q^T / 256 (dp4a GEMM) ---------------------
__global__ __launch_bounds__(256, 2) void k_gemm_I() {
    extern __shared__ char sm[];
    int* xsm = (int*)sm;              // [128][64] words
    int* wsm = (int*)(sm + 32768);    // [64][129] words (padded)
    int t = threadIdx.x;
    int rt0 = blockIdx.y * 128;
    int ht0 = blockIdx.x * 128;
    const int* Xw = (const int*)g_Xq;
    const int* Ww = (const int*)g_W2q;
    for (int idx = t; idx < 8192; idx += 256) {
        int r = idx >> 6, kc = idx & 63;
        xsm[r * 64 + kc] = Xw[(rt0 + r) * 64 + kc];
        wsm[kc * 129 + r] = Ww[(ht0 + r) * 64 + kc];
    }
    __syncthreads();
    int tx = t & 15, ty = t >> 4;
    int acc[8][8];
#pragma unroll
    for (int i = 0; i < 8; i++)
#pragma unroll
        for (int j = 0; j < 8; j++) acc[i][j] = 0;

    for (int kc = 0; kc < 64; kc++) {
        int a[8], b[8];
#pragma unroll
        for (int i = 0; i < 8; i++) a[i] = xsm[(ty * 8 + i) * 64 + kc];
#pragma unroll
        for (int j = 0; j < 8; j++) b[j] = wsm[kc * 129 + tx + 16 * j];
#pragma unroll
        for (int i = 0; i < 8; i++)
#pragma unroll
            for (int j = 0; j < 8; j++) acc[i][j] = __dp4a(a[i], b[j], acc[i][j]);
    }
#pragma unroll
    for (int i = 0; i < 8; i++)
#pragma unroll
        for (int j = 0; j < 8; j++)
            g_I[(size_t)(rt0 + ty * 8 + i) * 1024 + ht0 + tx + 16 * j] =
                (float)acc[i][j] * (1.f / 256.f);
}

// ---------------- K3: recurrent LIF scan ----------------------------------
// 16 clusters x 8 CTAs. CTA: 128-row slice of Wrq in SMEM ([c][h] int4 layout,
// pad 129), 8 batch elements. Spikes packed to bits, exchanged via DSMEM,
// one cluster.sync per step. Integer GEMV via dp4a; fp32 update replicates
// reference op order exactly.
__global__ void __cluster_dims__(8, 1, 1) __launch_bounds__(256, 1)
k_scan(const float* __restrict__ b2, const float* __restrict__ br2)
{
    extern __shared__ char sm[];
    int4*     wrT  = (int4*)sm;                   // [64][129] int4 = 132096 B
    unsigned* spkb = (unsigned*)(sm + 132096);    // [8][256] words = 8192 B
    unsigned* pk   = (unsigned*)(sm + 140288);    // [2][8][32]     = 2048 B
    int*      red  = (int*)(sm + 142336);         // [8][128]       = 4096 B
    float*    b2s  = (float*)(sm + 146432);       // 512 B
    float*    brs  = (float*)(sm + 146944);       // 512 B  (total 147456)

    cg::cluster_group cluster = cg::this_cluster();
    int cr = cluster.block_rank();
    int b0 = (blockIdx.x >> 3) * 8;
    int h0 = cr * 128;
    int t = threadIdx.x;

    const int4* Wr4 = (const int4*)g_Wrq;
    for (int idx = t; idx < 8192; idx += 256) {
        int h = idx >> 6, c = idx & 63;
        wrT[c * 129 + h] = Wr4[(h0 + h) * 64 + c];
    }
    if (t < 128) { b2s[t] = b2[h0 + t]; brs[t] = br2[h0 + t]; }
    for (int i = t; i < 512; i += 256) pk[i] = 0u;
    __syncthreads();
    cluster.sync();

    int h = t & 127;
    int half = t >> 7;
    int lane = t & 31;
    int warp = t >> 5;
    float mem[8], spf[8];
    int cnt[8];
#pragma unroll
    for (int b = 0; b < 8; b++) { mem[b] = 0.f; spf[b] = 0.f; cnt[b] = 0; }

    for (int step = 0; step < 1024; step++) {
        // unpack previous spikes (bits -> 0/1 bytes)
        {
            int bb = t >> 5;
            int wi = t & 31;
            unsigned w = pk[(step & 1) * 256 + bb * 32 + wi];
#pragma unroll
            for (int k = 0; k < 8; k++) {
                unsigned u = (w >> (4 * k)) & 0xFu;
                unsigned word = (u & 1u) | ((u << 7) & 0x100u) |
                                ((u << 14) & 0x10000u) | ((u << 21) & 0x1000000u);
                spkb[bb * 256 + wi * 8 + k] = word;
            }
        }
        __syncthreads();

        // prefetch feed-forward currents (exact, precomputed)
        float Iv[8];
        if (half == 0) {
            const float* Ibase = g_I + ((size_t)step * 128 + b0) * 1024 + h0 + h;
#pragma unroll
            for (int b = 0; b < 8; b++) Iv[b] = Ibase[(size_t)b * 1024];
        }

        // r16[b] = sum_j spike[b][j] * Wr16[h][j]  (this thread: half of K)
        int acc[8];
#pragma unroll
        for (int b = 0; b < 8; b++) acc[b] = 0;
        const int4* sp4 = (const int4*)spkb;   // [8][64] int4
        int cbase = half * 32;
#pragma unroll 4
        for (int jc = 0; jc < 32; jc++) {
            int4 w = wrT[(cbase + jc) * 129 + h];
#pragma unroll
            for (int b = 0; b < 8; b++) {
                int4 s = sp4[b * 64 + cbase + jc];
                acc[b] = __dp4a(w.x, s.x, acc[b]);
                acc[b] = __dp4a(w.y, s.y, acc[b]);
                acc[b] = __dp4a(w.z, s.z, acc[b]);
                acc[b] = __dp4a(w.w, s.w, acc[b]);
            }
        }
        if (half == 1) {
#pragma unroll
            for (int b = 0; b < 8; b++) red[b * 128 + h] = acc[b];
        }
        __syncthreads();

        if (half == 0) {
            unsigned bal[8];
#pragma unroll
            for (int b = 0; b < 8; b++) {
                int a = acc[b] + red[b * 128 + h];
                float R = (float)a * 0.0625f;               // exact
                float m = __fmul_rn(mem[b], 0.2f);
                if (spf[b] != 0.f) m = 0.f;                 // *(1-spike), exact
                m = __fadd_rn(m, Iv[b]);
                m = __fadd_rn(m, b2s[h]);
                m = __fadd_rn(m, R);
                m = __fadd_rn(m, brs[h]);
                mem[b] = m;
                bool s = m > 0.5f;
                spf[b] = s ? 1.f : 0.f;
                cnt[b] += s ? 1 : 0;
                bal[b] = __ballot_sync(0xffffffffu, s);
            }
            if (lane < 8) {
                unsigned word = bal[lane];
                int dsti = ((step + 1) & 1) * 256 + lane * 32 + cr * 4 + warp;
#pragma unroll
                for (int rk = 0; rk < 8; rk++) {
                    unsigned* dst = (unsigned*)cluster.map_shared_rank(
                        (void*)(pk + dsti), rk);
                    *dst = word;
                }
            }
        }
        cluster.sync();
    }

    if (half == 0) {
#pragma unroll
        for (int b = 0; b < 8; b++)
            g_sum[(b0 + b) * 1024 + h0 + h] = (float)cnt[b];
    }
}

// ---------------- K4: readout ---------------------------------------------
__global__ void k_out(const float* __restrict__ W3, const float* __restrict__ b3,
                      float* __restrict__ out)
{
    __shared__ float s0[128], s1[128];
    int b = blockIdx.x, t = threadIdx.x;
    float a0 = 0.f, a1 = 0.f;
    for (int hh = t; hh < 1024; hh += 128) {
        float s = g_sum[b * 1024 + hh];
        a0 += s * W3[hh];
        a1 += s * W3[1024 + hh];
    }
    s0[t] = a0; s1[t] = a1;
    __syncthreads();
    for (int o = 64; o > 0; o >>= 1) {
        if (t < o) { s0[t] += s0[t + o]; s1[t] += s1[t + o]; }
        __syncthreads();
    }
    if (t == 0) {
        out[b * 2 + 0] = s0[0] + b3[0];
        out[b * 2 + 1] = s1[0] + b3[1];
    }
}

// ---------------- launch ----------------------------------------------------
extern "C" void kernel_launch(void* const* d_in, const int* in_sizes, int n_in,
                              void* d_out, int out_size)
{
    const int*   inputs = (const int*)d_in[0];
    const float* emb    = (const float*)d_in[1];
    const float* W1     = (const float*)d_in[2];
    const float* b1     = (const float*)d_in[3];
    const float* W2     = (const float*)d_in[4];
    const float* b2     = (const float*)d_in[5];
    const float* Wr2    = (const float*)d_in[6];
    const float* br2    = (const float*)d_in[7];
    const float* W3     = (const float*)d_in[8];
    const float* b3     = (const float*)d_in[9];
    float* out = (float*)d_out;

    cudaFuncSetAttribute(k_embed_l1, cudaFuncAttributeMaxDynamicSharedMemorySize, 131072);
    cudaFuncSetAttribute(k_gemm_I,  cudaFuncAttributeMaxDynamicSharedMemorySize, 66560);
    cudaFuncSetAttribute(k_scan,    cudaFuncAttributeMaxDynamicSharedMemorySize, 147456);

    k_quant<<<(H_ * H_ + 255) / 256, 256>>>(W2, Wr2);
    k_embed_l1<<<2048, 256, 130816>>>(inputs, emb, W1, b1);
    k_gemm_I<<<dim3(8, 1024), 256, 65792>>>();
    k_scan<<<128, 256, 147456>>>(b2, br2);
    k_out<<<128, 128>>>(W3, b3, out);
}